// round 8
// baseline (speedup 1.0000x reference)
#include <cuda_runtime.h>
#include <cuda_bf16.h>
#include <cuda_fp16.h>
#include <math.h>
#include <stdint.h>

#define N_NODES 50000
#define D 128
#define EPS 1e-5f
#define E_MAX 800000

// padded bf16 tile: 128 rows x 64 cols, row stride 72 elems (144B = 9*16B -> bank rotate)
#define TROW 144
#define TILE_BYTES (128 * TROW)   // 18432

// ================= scratch (allocation-free: __device__ globals) =================
__device__ __half g_h16[N_NODES * D];   // fp16 hidden (only consumer: gather)
__device__ float g_agg[N_NODES * D];
__device__ float g_rst[N_NODES * D];
__device__ int   g_cnt[N_NODES];
__device__ int   g_off[N_NODES + 1];
__device__ uint2 g_edge[E_MAX];         // packed (src, w_bits), dst-sorted
__device__ float g_sum1[D], g_sq1[D], g_sum2[D], g_sq2[D];
__device__ float g_a1[D], g_b1[D], g_a2[D], g_b2[D];
__device__ unsigned char g_B1img[2][2][TILE_BYTES];
__device__ unsigned char g_B2img[4][2][TILE_BYTES];

// ================= warp-mma helpers =================
__device__ __forceinline__ uint32_t smem_u32(const void* p) {
    uint32_t a;
    asm("{ .reg .u64 t; cvta.to.shared.u64 t, %1; cvt.u32.u64 %0, t; }" : "=r"(a) : "l"(p));
    return a;
}
__device__ __forceinline__ void ldsm_x4(uint32_t* r, uint32_t addr) {
    asm volatile("ldmatrix.sync.aligned.m8n8.x4.shared.b16 {%0,%1,%2,%3}, [%4];"
                 : "=r"(r[0]), "=r"(r[1]), "=r"(r[2]), "=r"(r[3]) : "r"(addr));
}
__device__ __forceinline__ void mma_bf16(float* d, const uint32_t* a, const uint32_t* b) {
    asm volatile(
        "mma.sync.aligned.m16n8k16.row.col.f32.bf16.bf16.f32 "
        "{%0,%1,%2,%3}, {%4,%5,%6,%7}, {%8,%9}, {%0,%1,%2,%3};"
        : "+f"(d[0]), "+f"(d[1]), "+f"(d[2]), "+f"(d[3])
        : "r"(a[0]), "r"(a[1]), "r"(a[2]), "r"(a[3]), "r"(b[0]), "r"(b[1]));
}

// ================= zero per-replay accumulators =================
__global__ void zero_kernel() {
    int idx = blockIdx.x * blockDim.x + threadIdx.x;
    int tot = blockDim.x * gridDim.x;
    for (int i = idx; i < N_NODES; i += tot) g_cnt[i] = 0;
    if (idx < D) { g_sum1[idx] = 0.f; g_sq1[idx] = 0.f; g_sum2[idx] = 0.f; g_sq2[idx] = 0.f; }
}

// ================= weight prep: split fp32 -> (bf16 hi, bf16 lo), padded layout =================
__global__ void prep_B(const float* __restrict__ Qw, const float* __restrict__ Ww) {
    int idx = blockIdx.x * blockDim.x + threadIdx.x;
    if (idx < 16384) {
        int r = idx >> 7, k = idx & 127;
        int chunk = k >> 6, kk = k & 63;
        float x = Qw[r * 128 + k];
        __nv_bfloat16 hi = __float2bfloat16_rn(x);
        __nv_bfloat16 lo = __float2bfloat16_rn(x - __bfloat162float(hi));
        uint32_t off = (uint32_t)(r * TROW + kk * 2);
        *(__nv_bfloat16*)(&g_B1img[chunk][0][off]) = hi;
        *(__nv_bfloat16*)(&g_B1img[chunk][1][off]) = lo;
    } else if (idx < 16384 + 32768) {
        int e = idx - 16384;
        int r = e >> 8, k = e & 255;
        int chunk = k >> 6, kk = k & 63;
        float x = Ww[r * 256 + k];
        __nv_bfloat16 hi = __float2bfloat16_rn(x);
        __nv_bfloat16 lo = __float2bfloat16_rn(x - __bfloat162float(hi));
        uint32_t off = (uint32_t)(r * TROW + kk * 2);
        *(__nv_bfloat16*)(&g_B2img[chunk][0][off]) = hi;
        *(__nv_bfloat16*)(&g_B2img[chunk][1][off]) = lo;
    }
}

// ================= HMMA GEMM: C = relu(A_concat @ B^T + bias), fused col stats =================
#define SM_BIAS 0
#define SM_SSUM 512
#define SM_SSQ  1024
#define SM_AHI  1536
#define SM_ALO  (SM_AHI + TILE_BYTES)
#define SM_BHI  (SM_AHI + 2 * TILE_BYTES)
#define SM_BLO  (SM_AHI + 3 * TILE_BYTES)
#define SM_TOTAL (SM_AHI + 4 * TILE_BYTES)

template <int PHASE>
__global__ __launch_bounds__(256) void hmma_gemm(const float* __restrict__ A,
                                                 const float* __restrict__ bias) {
    extern __shared__ char smem[];
    const uint32_t sbase = smem_u32(smem);
    const int tid = threadIdx.x;
    const int wid = tid >> 5;
    const int lane = tid & 31;
    const int r0 = blockIdx.x * 128;
    const int NC = (PHASE == 0) ? 2 : 4;

    if (tid < 128) {
        *(float*)(smem + SM_BIAS + tid * 4) = bias[tid];
        *(float*)(smem + SM_SSUM + tid * 4) = 0.f;
        *(float*)(smem + SM_SSQ + tid * 4) = 0.f;
    }

    const int frow = tid >> 1;
    const int fhalf = tid & 1;
    const bool fvalid = (r0 + frow < N_NODES);

    const int warp_m = wid & 3;
    const int warp_n = wid >> 2;
    const uint32_t a_off = (uint32_t)((warp_m * 32 + (lane & 15)) * TROW + (lane >> 4) * 16);
    const uint32_t b_off = (uint32_t)((warp_n * 64 + (lane & 7) + ((lane >> 4) << 3)) * TROW
                                      + ((lane >> 3) & 1) * 16);

    float acc[2][8][4];
#pragma unroll
    for (int mt = 0; mt < 2; mt++)
#pragma unroll
        for (int nt = 0; nt < 8; nt++)
#pragma unroll
            for (int q = 0; q < 4; q++) acc[mt][nt][q] = 0.f;

    for (int c = 0; c < NC; c++) {
        const float* Asrc;
        int kbase;
        if (PHASE == 0) { Asrc = A; kbase = c * 64; }
        else if (c < 2) { Asrc = A; kbase = c * 64; }
        else            { Asrc = g_agg; kbase = (c - 2) * 64; }

        const float* rp = Asrc + (size_t)(fvalid ? (r0 + frow) : 0) * 128 + kbase + fhalf * 32;
#pragma unroll
        for (int i = 0; i < 8; i++) {
            float4 v = fvalid ? *(const float4*)(rp + i * 4) : make_float4(0.f, 0.f, 0.f, 0.f);
            __nv_bfloat162 h01, h23, l01, l23;
            h01.x = __float2bfloat16_rn(v.x); h01.y = __float2bfloat16_rn(v.y);
            h23.x = __float2bfloat16_rn(v.z); h23.y = __float2bfloat16_rn(v.w);
            l01.x = __float2bfloat16_rn(v.x - __bfloat162float(h01.x));
            l01.y = __float2bfloat16_rn(v.y - __bfloat162float(h01.y));
            l23.x = __float2bfloat16_rn(v.z - __bfloat162float(h23.x));
            l23.y = __float2bfloat16_rn(v.w - __bfloat162float(h23.y));
            uint32_t off = (uint32_t)(frow * TROW + (fhalf * 32 + i * 4) * 2);
            *(__nv_bfloat162*)(smem + SM_AHI + off) = h01;
            *(__nv_bfloat162*)(smem + SM_AHI + off + 4) = h23;
            *(__nv_bfloat162*)(smem + SM_ALO + off) = l01;
            *(__nv_bfloat162*)(smem + SM_ALO + off + 4) = l23;
        }
        {
            const float4* bh = (PHASE == 0) ? (const float4*)g_B1img[c][0] : (const float4*)g_B2img[c][0];
            const float4* bl = (PHASE == 0) ? (const float4*)g_B1img[c][1] : (const float4*)g_B2img[c][1];
            float4* dh = (float4*)(smem + SM_BHI);
            float4* dl = (float4*)(smem + SM_BLO);
            const int nf4 = TILE_BYTES / 16;
            for (int j = tid; j < nf4; j += 256) {
                dh[j] = bh[j];
                dl[j] = bl[j];
            }
        }
        __syncthreads();

#pragma unroll
        for (int ks = 0; ks < 4; ks++) {
            uint32_t ah[2][4], al[2][4];
#pragma unroll
            for (int mt = 0; mt < 2; mt++) {
                uint32_t o = a_off + mt * (16 * TROW) + ks * 32;
                ldsm_x4(ah[mt], sbase + SM_AHI + o);
                ldsm_x4(al[mt], sbase + SM_ALO + o);
            }
            uint32_t bh[4][4], bl[4][4];
#pragma unroll
            for (int ng = 0; ng < 4; ng++) {
                uint32_t o = b_off + ng * (16 * TROW) + ks * 32;
                ldsm_x4(bh[ng], sbase + SM_BHI + o);
                ldsm_x4(bl[ng], sbase + SM_BLO + o);
            }
#pragma unroll
            for (int mt = 0; mt < 2; mt++)
#pragma unroll
                for (int ng = 0; ng < 4; ng++) {
                    mma_bf16(acc[mt][ng * 2 + 0], ah[mt], &bh[ng][0]);
                    mma_bf16(acc[mt][ng * 2 + 1], ah[mt], &bh[ng][2]);
                    mma_bf16(acc[mt][ng * 2 + 0], ah[mt], &bl[ng][0]);
                    mma_bf16(acc[mt][ng * 2 + 1], ah[mt], &bl[ng][2]);
                    mma_bf16(acc[mt][ng * 2 + 0], al[mt], &bh[ng][0]);
                    mma_bf16(acc[mt][ng * 2 + 1], al[mt], &bh[ng][2]);
                }
        }
        __syncthreads();
    }

    // ---- epilogue: bias + relu + store (fp16 phase0 / fp32 phase1) + fused col stats ----
    const int er = r0 + warp_m * 32 + (lane >> 2);
    const int ec = warp_n * 64 + (lane & 3) * 2;
#pragma unroll
    for (int nt = 0; nt < 8; nt++) {
        int col = ec + nt * 8;
        float bx = *(float*)(smem + SM_BIAS + col * 4);
        float by = *(float*)(smem + SM_BIAS + (col + 1) * 4);
        float csx = 0.f, csy = 0.f, cqx = 0.f, cqy = 0.f;
#pragma unroll
        for (int mt = 0; mt < 2; mt++) {
#pragma unroll
            for (int half = 0; half < 2; half++) {
                int row = er + mt * 16 + half * 8;
                if (row < N_NODES) {
                    float x = fmaxf(acc[mt][nt][half * 2 + 0] + bx, 0.f);
                    float y = fmaxf(acc[mt][nt][half * 2 + 1] + by, 0.f);
                    csx += x; cqx += x * x;
                    csy += y; cqy += y * y;
                    if (PHASE == 0) {
                        *(__half2*)(g_h16 + (size_t)row * 128 + col) = __floats2half2_rn(x, y);
                    } else {
                        float2 v; v.x = x; v.y = y;
                        *(float2*)(g_rst + (size_t)row * 128 + col) = v;
                    }
                }
            }
        }
        atomicAdd((float*)(smem + SM_SSUM + col * 4), csx);
        atomicAdd((float*)(smem + SM_SSUM + (col + 1) * 4), csy);
        atomicAdd((float*)(smem + SM_SSQ + col * 4), cqx);
        atomicAdd((float*)(smem + SM_SSQ + (col + 1) * 4), cqy);
    }
    __syncthreads();
    if (tid < 128) {
        float* gs = (PHASE == 0) ? g_sum1 : g_sum2;
        float* gq = (PHASE == 0) ? g_sq1 : g_sq2;
        atomicAdd(&gs[tid], *(float*)(smem + SM_SSUM + tid * 4));
        atomicAdd(&gq[tid], *(float*)(smem + SM_SSQ + tid * 4));
    }
}

// ================= BN params =================
__global__ void bn_params(int phase, const float* __restrict__ gamma,
                          const float* __restrict__ beta) {
    int c = threadIdx.x;
    const float* sum = phase ? g_sum2 : g_sum1;
    const float* sq  = phase ? g_sq2  : g_sq1;
    float* pa = phase ? g_a2 : g_a1;
    float* pb = phase ? g_b2 : g_b1;
    float mean = sum[c] * (1.f / N_NODES);
    float var = sq[c] * (1.f / N_NODES) - mean * mean;
    float rstd = rsqrtf(var + EPS);
    float a = gamma[c] * rstd;
    pa[c] = a;
    pb[c] = beta[c] - mean * a;
}

// ================= CSR build =================
__global__ void hist_kernel(const int* __restrict__ dst, int E) {
    int i = blockIdx.x * blockDim.x + threadIdx.x;
    if (i < E) atomicAdd(&g_cnt[dst[i]], 1);
}

// vectorized single-block scan: 4 elems/thread/iter -> 13 iterations
__global__ __launch_bounds__(1024) void prefix_kernel() {
    __shared__ int wsum[32];
    __shared__ int carry;
    int tid = threadIdx.x, lane = tid & 31, wid = tid >> 5;
    if (tid == 0) { carry = 0; g_off[0] = 0; }
    __syncthreads();
    for (int base = 0; base < N_NODES; base += 4096) {
        int i0 = base + tid * 4;
        int v[4];
#pragma unroll
        for (int j = 0; j < 4; j++) v[j] = (i0 + j < N_NODES) ? g_cnt[i0 + j] : 0;
        int local = v[0] + v[1] + v[2] + v[3];
        int x = local;
#pragma unroll
        for (int o = 1; o < 32; o <<= 1) {
            int y = __shfl_up_sync(0xFFFFFFFFu, x, o);
            if (lane >= o) x += y;
        }
        if (lane == 31) wsum[wid] = x;
        __syncthreads();
        if (wid == 0) {
            int s = wsum[lane];
#pragma unroll
            for (int o = 1; o < 32; o <<= 1) {
                int y = __shfl_up_sync(0xFFFFFFFFu, s, o);
                if (lane >= o) s += y;
            }
            wsum[lane] = s;
        }
        __syncthreads();
        int wbase = (wid == 0) ? 0 : wsum[wid - 1];
        int run = carry + wbase + x - local;   // exclusive prefix at i0
#pragma unroll
        for (int j = 0; j < 4; j++) {
            int i = i0 + j;
            if (i < N_NODES) {
                g_cnt[i] = run;          // cursor start (exclusive)
                g_off[i + 1] = run + v[j];
            }
            run += v[j];
        }
        __syncthreads();
        if (tid == 0) carry += wsum[31];
        __syncthreads();
    }
}

// packed scatter: one 8B store per edge
__global__ void scatter_kernel(const float* __restrict__ w, const int* __restrict__ src,
                               const int* __restrict__ dst, int E) {
    int i = blockIdx.x * blockDim.x + threadIdx.x;
    if (i >= E) return;
    int d = dst[i];
    int pos = atomicAdd(&g_cnt[d], 1);
    g_edge[pos] = make_uint2((uint32_t)src[i], __float_as_uint(w[i]));
}

// ================= gather (fp16 h) + BN1 fold: warp per dst node =================
__global__ void gather_kernel() {
    int gw = (blockIdx.x * blockDim.x + threadIdx.x) >> 5;
    int lane = threadIdx.x & 31;
    if (gw >= N_NODES) return;
    int beg = g_off[gw], end = g_off[gw + 1];
    float a0 = 0.f, a1v = 0.f, a2v = 0.f, a3v = 0.f;
    float den = 0.f;
    for (int j = beg; j < end; j++) {
        uint2 e = g_edge[j];                       // warp-uniform broadcast
        float we = __uint_as_float(e.y);
        uint2 hp = ((const uint2*)(g_h16 + (size_t)e.x * 128))[lane];   // 4 halves
        float2 f0 = __half22float2(*(const __half2*)&hp.x);
        float2 f1 = __half22float2(*(const __half2*)&hp.y);
        a0 += we * f0.x; a1v += we * f0.y;
        a2v += we * f1.x; a3v += we * f1.y;
        den += we;
    }
    float4 a = ((const float4*)g_a1)[lane];
    float4 b = ((const float4*)g_b1)[lane];
    float4 v;
    if (den != 0.f) {
        float inv = 1.f / den;
        v.x = a.x * (a0 * inv) + b.x;
        v.y = a.y * (a1v * inv) + b.y;
        v.z = a.z * (a2v * inv) + b.z;
        v.w = a.w * (a3v * inv) + b.w;
    } else {
        uint2 hp = ((const uint2*)(g_h16 + (size_t)gw * 128))[lane];
        float2 f0 = __half22float2(*(const __half2*)&hp.x);
        float2 f1 = __half22float2(*(const __half2*)&hp.y);
        v.x = a.x * f0.x + b.x;
        v.y = a.y * f0.y + b.y;
        v.z = a.z * f1.x + b.z;
        v.w = a.w * f1.y + b.w;
    }
    ((float4*)g_agg)[(size_t)gw * 32 + lane] = v;
}

// ================= BN2 + L2 normalize =================
__global__ void final_kernel(float* __restrict__ out) {
    int gw = (blockIdx.x * blockDim.x + threadIdx.x) >> 5;
    int lane = threadIdx.x & 31;
    if (gw >= N_NODES) return;
    float4 a = ((const float4*)g_a2)[lane];
    float4 b = ((const float4*)g_b2)[lane];
    float4 v = ((const float4*)g_rst)[(size_t)gw * 32 + lane];
    v.x = v.x * a.x + b.x; v.y = v.y * a.y + b.y;
    v.z = v.z * a.z + b.z; v.w = v.w * a.w + b.w;
    float ss = v.x * v.x + v.y * v.y + v.z * v.z + v.w * v.w;
#pragma unroll
    for (int o = 16; o > 0; o >>= 1) ss += __shfl_xor_sync(0xFFFFFFFFu, ss, o);
    float norm = sqrtf(ss);
    float inv = (norm == 0.f) ? 1.f : 1.f / norm;
    v.x *= inv; v.y *= inv; v.z *= inv; v.w *= inv;
    ((float4*)out)[(size_t)gw * 32 + lane] = v;
}

extern "C" void kernel_launch(void* const* d_in, const int* in_sizes, int n_in,
                              void* d_out, int out_size) {
    const float* feat  = (const float*)d_in[0];
    const float* w     = (const float*)d_in[1];
    const float* Qw    = (const float*)d_in[2];
    const float* Qb    = (const float*)d_in[3];
    const float* Ww    = (const float*)d_in[4];
    const float* Wb    = (const float*)d_in[5];
    const float* gamma = (const float*)d_in[6];
    const float* beta  = (const float*)d_in[7];
    const int* src     = (const int*)d_in[8];
    const int* dst     = (const int*)d_in[9];
    const int E = in_sizes[1];
    float* out = (float*)d_out;

    static int smem_set = 0;
    if (!smem_set) {
        cudaFuncSetAttribute(hmma_gemm<0>, cudaFuncAttributeMaxDynamicSharedMemorySize, SM_TOTAL);
        cudaFuncSetAttribute(hmma_gemm<1>, cudaFuncAttributeMaxDynamicSharedMemorySize, SM_TOTAL);
        smem_set = 1;
    }

    const int tile_grid = (N_NODES + 127) / 128;        // 391
    const int warp_grid = (N_NODES * 32 + 255) / 256;   // 6250
    const int e_grid = (E + 255) / 256;

    zero_kernel<<<128, 256>>>();
    hist_kernel<<<e_grid, 256>>>(dst, E);
    prefix_kernel<<<1, 1024>>>();
    scatter_kernel<<<e_grid, 256>>>(w, src, dst, E);
    prep_B<<<192, 256>>>(Qw, Ww);
    hmma_gemm<0><<<tile_grid, 256, SM_TOTAL>>>(feat, Qb);
    bn_params<<<1, 128>>>(0, gamma, beta);
    gather_kernel<<<warp_grid, 256>>>();
    hmma_gemm<1><<<tile_grid, 256, SM_TOTAL>>>(feat, Wb);
    bn_params<<<1, 128>>>(1, gamma, beta);
    final_kernel<<<warp_grid, 256>>>(out);
}

// round 9
// speedup vs baseline: 1.2733x; 1.2733x over previous
#include <cuda_runtime.h>
#include <cuda_bf16.h>
#include <cuda_fp16.h>
#include <math.h>
#include <stdint.h>

#define N_NODES 50000
#define D 128
#define EPS 1e-5f
#define E_MAX 800000

// padded bf16 tile: 128 rows x 64 cols, row stride 72 elems (144B = 9*16B -> bank rotate)
#define TROW 144
#define TILE_BYTES (128 * TROW)   // 18432

// ================= scratch (allocation-free: __device__ globals) =================
__device__ __half g_h16[N_NODES * D];   // fp16 hidden (consumers: gather, stats16)
__device__ float g_agg[N_NODES * D];
__device__ float g_rst[N_NODES * D];
__device__ int   g_cnt[N_NODES];
__device__ int   g_off[N_NODES + 1];
__device__ uint2 g_edge[E_MAX];         // packed (src, w_bits), dst-sorted
__device__ float g_sum1[D], g_sq1[D], g_sum2[D], g_sq2[D];
__device__ float g_a1[D], g_b1[D], g_a2[D], g_b2[D];
__device__ unsigned char g_B1img[2][2][TILE_BYTES];
__device__ unsigned char g_B2img[4][2][TILE_BYTES];

// ================= warp-mma helpers =================
__device__ __forceinline__ uint32_t smem_u32(const void* p) {
    uint32_t a;
    asm("{ .reg .u64 t; cvta.to.shared.u64 t, %1; cvt.u32.u64 %0, t; }" : "=r"(a) : "l"(p));
    return a;
}
__device__ __forceinline__ void ldsm_x4(uint32_t* r, uint32_t addr) {
    asm volatile("ldmatrix.sync.aligned.m8n8.x4.shared.b16 {%0,%1,%2,%3}, [%4];"
                 : "=r"(r[0]), "=r"(r[1]), "=r"(r[2]), "=r"(r[3]) : "r"(addr));
}
__device__ __forceinline__ void mma_bf16(float* d, const uint32_t* a, const uint32_t* b) {
    asm volatile(
        "mma.sync.aligned.m16n8k16.row.col.f32.bf16.bf16.f32 "
        "{%0,%1,%2,%3}, {%4,%5,%6,%7}, {%8,%9}, {%0,%1,%2,%3};"
        : "+f"(d[0]), "+f"(d[1]), "+f"(d[2]), "+f"(d[3])
        : "r"(a[0]), "r"(a[1]), "r"(a[2]), "r"(a[3]), "r"(b[0]), "r"(b[1]));
}

// ================= zero per-replay accumulators =================
__global__ void zero_kernel() {
    int idx = blockIdx.x * blockDim.x + threadIdx.x;
    int tot = blockDim.x * gridDim.x;
    for (int i = idx; i < N_NODES; i += tot) g_cnt[i] = 0;
    if (idx < D) { g_sum1[idx] = 0.f; g_sq1[idx] = 0.f; g_sum2[idx] = 0.f; g_sq2[idx] = 0.f; }
}

// ================= weight prep: split fp32 -> (bf16 hi, bf16 lo), padded layout =================
__global__ void prep_B(const float* __restrict__ Qw, const float* __restrict__ Ww) {
    int idx = blockIdx.x * blockDim.x + threadIdx.x;
    if (idx < 16384) {
        int r = idx >> 7, k = idx & 127;
        int chunk = k >> 6, kk = k & 63;
        float x = Qw[r * 128 + k];
        __nv_bfloat16 hi = __float2bfloat16_rn(x);
        __nv_bfloat16 lo = __float2bfloat16_rn(x - __bfloat162float(hi));
        uint32_t off = (uint32_t)(r * TROW + kk * 2);
        *(__nv_bfloat16*)(&g_B1img[chunk][0][off]) = hi;
        *(__nv_bfloat16*)(&g_B1img[chunk][1][off]) = lo;
    } else if (idx < 16384 + 32768) {
        int e = idx - 16384;
        int r = e >> 8, k = e & 255;
        int chunk = k >> 6, kk = k & 63;
        float x = Ww[r * 256 + k];
        __nv_bfloat16 hi = __float2bfloat16_rn(x);
        __nv_bfloat16 lo = __float2bfloat16_rn(x - __bfloat162float(hi));
        uint32_t off = (uint32_t)(r * TROW + kk * 2);
        *(__nv_bfloat16*)(&g_B2img[chunk][0][off]) = hi;
        *(__nv_bfloat16*)(&g_B2img[chunk][1][off]) = lo;
    }
}

// ================= HMMA GEMM: C = relu(A_concat @ B^T + bias) =================
// (pure epilogue — stats handled by separate streaming kernels; R8's fused smem
//  atomics suspected as the regression)
#define SM_BIAS 0
#define SM_AHI  1024
#define SM_ALO  (SM_AHI + TILE_BYTES)
#define SM_BHI  (SM_AHI + 2 * TILE_BYTES)
#define SM_BLO  (SM_AHI + 3 * TILE_BYTES)
#define SM_TOTAL (SM_AHI + 4 * TILE_BYTES)   // 74752

template <int PHASE>
__global__ __launch_bounds__(256) void hmma_gemm(const float* __restrict__ A,
                                                 const float* __restrict__ bias) {
    extern __shared__ char smem[];
    const uint32_t sbase = smem_u32(smem);
    const int tid = threadIdx.x;
    const int wid = tid >> 5;
    const int lane = tid & 31;
    const int r0 = blockIdx.x * 128;
    const int NC = (PHASE == 0) ? 2 : 4;

    if (tid < 128) *(float*)(smem + SM_BIAS + tid * 4) = bias[tid];

    const int frow = tid >> 1;
    const int fhalf = tid & 1;
    const bool fvalid = (r0 + frow < N_NODES);

    const int warp_m = wid & 3;
    const int warp_n = wid >> 2;
    const uint32_t a_off = (uint32_t)((warp_m * 32 + (lane & 15)) * TROW + (lane >> 4) * 16);
    const uint32_t b_off = (uint32_t)((warp_n * 64 + (lane & 7) + ((lane >> 4) << 3)) * TROW
                                      + ((lane >> 3) & 1) * 16);

    float acc[2][8][4];
#pragma unroll
    for (int mt = 0; mt < 2; mt++)
#pragma unroll
        for (int nt = 0; nt < 8; nt++)
#pragma unroll
            for (int q = 0; q < 4; q++) acc[mt][nt][q] = 0.f;

    for (int c = 0; c < NC; c++) {
        const float* Asrc;
        int kbase;
        if (PHASE == 0) { Asrc = A; kbase = c * 64; }
        else if (c < 2) { Asrc = A; kbase = c * 64; }
        else            { Asrc = g_agg; kbase = (c - 2) * 64; }

        const float* rp = Asrc + (size_t)(fvalid ? (r0 + frow) : 0) * 128 + kbase + fhalf * 32;
#pragma unroll
        for (int i = 0; i < 8; i++) {
            float4 v = fvalid ? *(const float4*)(rp + i * 4) : make_float4(0.f, 0.f, 0.f, 0.f);
            __nv_bfloat162 h01, h23, l01, l23;
            h01.x = __float2bfloat16_rn(v.x); h01.y = __float2bfloat16_rn(v.y);
            h23.x = __float2bfloat16_rn(v.z); h23.y = __float2bfloat16_rn(v.w);
            l01.x = __float2bfloat16_rn(v.x - __bfloat162float(h01.x));
            l01.y = __float2bfloat16_rn(v.y - __bfloat162float(h01.y));
            l23.x = __float2bfloat16_rn(v.z - __bfloat162float(h23.x));
            l23.y = __float2bfloat16_rn(v.w - __bfloat162float(h23.y));
            uint32_t off = (uint32_t)(frow * TROW + (fhalf * 32 + i * 4) * 2);
            *(__nv_bfloat162*)(smem + SM_AHI + off) = h01;
            *(__nv_bfloat162*)(smem + SM_AHI + off + 4) = h23;
            *(__nv_bfloat162*)(smem + SM_ALO + off) = l01;
            *(__nv_bfloat162*)(smem + SM_ALO + off + 4) = l23;
        }
        {
            const float4* bh = (PHASE == 0) ? (const float4*)g_B1img[c][0] : (const float4*)g_B2img[c][0];
            const float4* bl = (PHASE == 0) ? (const float4*)g_B1img[c][1] : (const float4*)g_B2img[c][1];
            float4* dh = (float4*)(smem + SM_BHI);
            float4* dl = (float4*)(smem + SM_BLO);
            const int nf4 = TILE_BYTES / 16;
            for (int j = tid; j < nf4; j += 256) {
                dh[j] = bh[j];
                dl[j] = bl[j];
            }
        }
        __syncthreads();

#pragma unroll
        for (int ks = 0; ks < 4; ks++) {
            uint32_t ah[2][4], al[2][4];
#pragma unroll
            for (int mt = 0; mt < 2; mt++) {
                uint32_t o = a_off + mt * (16 * TROW) + ks * 32;
                ldsm_x4(ah[mt], sbase + SM_AHI + o);
                ldsm_x4(al[mt], sbase + SM_ALO + o);
            }
            uint32_t bh[4][4], bl[4][4];
#pragma unroll
            for (int ng = 0; ng < 4; ng++) {
                uint32_t o = b_off + ng * (16 * TROW) + ks * 32;
                ldsm_x4(bh[ng], sbase + SM_BHI + o);
                ldsm_x4(bl[ng], sbase + SM_BLO + o);
            }
#pragma unroll
            for (int mt = 0; mt < 2; mt++)
#pragma unroll
                for (int ng = 0; ng < 4; ng++) {
                    mma_bf16(acc[mt][ng * 2 + 0], ah[mt], &bh[ng][0]);
                    mma_bf16(acc[mt][ng * 2 + 1], ah[mt], &bh[ng][2]);
                    mma_bf16(acc[mt][ng * 2 + 0], ah[mt], &bl[ng][0]);
                    mma_bf16(acc[mt][ng * 2 + 1], ah[mt], &bl[ng][2]);
                    mma_bf16(acc[mt][ng * 2 + 0], al[mt], &bh[ng][0]);
                    mma_bf16(acc[mt][ng * 2 + 1], al[mt], &bh[ng][2]);
                }
        }
        __syncthreads();
    }

    // ---- epilogue: bias + relu + store (fp16 phase0 / fp32 phase1) ----
    const int er = r0 + warp_m * 32 + (lane >> 2);
    const int ec = warp_n * 64 + (lane & 3) * 2;
#pragma unroll
    for (int mt = 0; mt < 2; mt++) {
#pragma unroll
        for (int nt = 0; nt < 8; nt++) {
            int col = ec + nt * 8;
            float bx = *(float*)(smem + SM_BIAS + col * 4);
            float by = *(float*)(smem + SM_BIAS + (col + 1) * 4);
#pragma unroll
            for (int half = 0; half < 2; half++) {
                int row = er + mt * 16 + half * 8;
                if (row < N_NODES) {
                    float x = fmaxf(acc[mt][nt][half * 2 + 0] + bx, 0.f);
                    float y = fmaxf(acc[mt][nt][half * 2 + 1] + by, 0.f);
                    if (PHASE == 0) {
                        *(__half2*)(g_h16 + (size_t)row * 128 + col) = __floats2half2_rn(x, y);
                    } else {
                        float2 v; v.x = x; v.y = y;
                        *(float2*)(g_rst + (size_t)row * 128 + col) = v;
                    }
                }
            }
        }
    }
}

// ================= column stats (phase 0: fp16 input) =================
__global__ void stats16_kernel() {
    __shared__ float s_s[128], s_q[128];
    int tid = threadIdx.x;
    if (tid < 128) { s_s[tid] = 0.f; s_q[tid] = 0.f; }
    __syncthreads();
    int lane = tid & 31;
    int wg = (blockIdx.x * blockDim.x + tid) >> 5;
    int wt = (gridDim.x * blockDim.x) >> 5;
    float4 s = make_float4(0.f, 0.f, 0.f, 0.f);
    float4 q = make_float4(0.f, 0.f, 0.f, 0.f);
    for (int r = wg; r < N_NODES; r += wt) {
        uint2 hp = ((const uint2*)(g_h16 + (size_t)r * 128))[lane];
        float2 f0 = __half22float2(*(const __half2*)&hp.x);
        float2 f1 = __half22float2(*(const __half2*)&hp.y);
        s.x += f0.x; s.y += f0.y; s.z += f1.x; s.w += f1.y;
        q.x += f0.x * f0.x; q.y += f0.y * f0.y;
        q.z += f1.x * f1.x; q.w += f1.y * f1.y;
    }
    atomicAdd(&s_s[lane * 4 + 0], s.x); atomicAdd(&s_s[lane * 4 + 1], s.y);
    atomicAdd(&s_s[lane * 4 + 2], s.z); atomicAdd(&s_s[lane * 4 + 3], s.w);
    atomicAdd(&s_q[lane * 4 + 0], q.x); atomicAdd(&s_q[lane * 4 + 1], q.y);
    atomicAdd(&s_q[lane * 4 + 2], q.z); atomicAdd(&s_q[lane * 4 + 3], q.w);
    __syncthreads();
    if (tid < 128) {
        atomicAdd(&g_sum1[tid], s_s[tid]);
        atomicAdd(&g_sq1[tid], s_q[tid]);
    }
}

// ================= column stats (phase 1: fp32 g_rst) =================
__global__ void stats32_kernel() {
    __shared__ float s_s[128], s_q[128];
    int tid = threadIdx.x;
    if (tid < 128) { s_s[tid] = 0.f; s_q[tid] = 0.f; }
    __syncthreads();
    int lane = tid & 31;
    int wg = (blockIdx.x * blockDim.x + tid) >> 5;
    int wt = (gridDim.x * blockDim.x) >> 5;
    float4 s = make_float4(0.f, 0.f, 0.f, 0.f);
    float4 q = make_float4(0.f, 0.f, 0.f, 0.f);
    for (int r = wg; r < N_NODES; r += wt) {
        float4 v = ((const float4*)g_rst)[(size_t)r * 32 + lane];
        s.x += v.x; s.y += v.y; s.z += v.z; s.w += v.w;
        q.x += v.x * v.x; q.y += v.y * v.y; q.z += v.z * v.z; q.w += v.w * v.w;
    }
    atomicAdd(&s_s[lane * 4 + 0], s.x); atomicAdd(&s_s[lane * 4 + 1], s.y);
    atomicAdd(&s_s[lane * 4 + 2], s.z); atomicAdd(&s_s[lane * 4 + 3], s.w);
    atomicAdd(&s_q[lane * 4 + 0], q.x); atomicAdd(&s_q[lane * 4 + 1], q.y);
    atomicAdd(&s_q[lane * 4 + 2], q.z); atomicAdd(&s_q[lane * 4 + 3], q.w);
    __syncthreads();
    if (tid < 128) {
        atomicAdd(&g_sum2[tid], s_s[tid]);
        atomicAdd(&g_sq2[tid], s_q[tid]);
    }
}

// ================= BN params =================
__global__ void bn_params(int phase, const float* __restrict__ gamma,
                          const float* __restrict__ beta) {
    int c = threadIdx.x;
    const float* sum = phase ? g_sum2 : g_sum1;
    const float* sq  = phase ? g_sq2  : g_sq1;
    float* pa = phase ? g_a2 : g_a1;
    float* pb = phase ? g_b2 : g_b1;
    float mean = sum[c] * (1.f / N_NODES);
    float var = sq[c] * (1.f / N_NODES) - mean * mean;
    float rstd = rsqrtf(var + EPS);
    float a = gamma[c] * rstd;
    pa[c] = a;
    pb[c] = beta[c] - mean * a;
}

// ================= CSR build =================
__global__ void hist_kernel(const int* __restrict__ dst, int E) {
    int i = blockIdx.x * blockDim.x + threadIdx.x;
    if (i < E) atomicAdd(&g_cnt[dst[i]], 1);
}

__global__ __launch_bounds__(1024) void prefix_kernel() {
    __shared__ int wsum[32];
    __shared__ int carry;
    int tid = threadIdx.x, lane = tid & 31, wid = tid >> 5;
    if (tid == 0) { carry = 0; g_off[0] = 0; }
    __syncthreads();
    for (int base = 0; base < N_NODES; base += 4096) {
        int i0 = base + tid * 4;
        int v[4];
#pragma unroll
        for (int j = 0; j < 4; j++) v[j] = (i0 + j < N_NODES) ? g_cnt[i0 + j] : 0;
        int local = v[0] + v[1] + v[2] + v[3];
        int x = local;
#pragma unroll
        for (int o = 1; o < 32; o <<= 1) {
            int y = __shfl_up_sync(0xFFFFFFFFu, x, o);
            if (lane >= o) x += y;
        }
        if (lane == 31) wsum[wid] = x;
        __syncthreads();
        if (wid == 0) {
            int s = wsum[lane];
#pragma unroll
            for (int o = 1; o < 32; o <<= 1) {
                int y = __shfl_up_sync(0xFFFFFFFFu, s, o);
                if (lane >= o) s += y;
            }
            wsum[lane] = s;
        }
        __syncthreads();
        int wbase = (wid == 0) ? 0 : wsum[wid - 1];
        int run = carry + wbase + x - local;
#pragma unroll
        for (int j = 0; j < 4; j++) {
            int i = i0 + j;
            if (i < N_NODES) {
                g_cnt[i] = run;
                g_off[i + 1] = run + v[j];
            }
            run += v[j];
        }
        __syncthreads();
        if (tid == 0) carry += wsum[31];
        __syncthreads();
    }
}

__global__ void scatter_kernel(const float* __restrict__ w, const int* __restrict__ src,
                               const int* __restrict__ dst, int E) {
    int i = blockIdx.x * blockDim.x + threadIdx.x;
    if (i >= E) return;
    int d = dst[i];
    int pos = atomicAdd(&g_cnt[d], 1);
    g_edge[pos] = make_uint2((uint32_t)src[i], __float_as_uint(w[i]));
}

// ================= gather (fp16 h, 2x unrolled for MLP) + BN1 fold =================
__global__ void gather_kernel() {
    int gw = (blockIdx.x * blockDim.x + threadIdx.x) >> 5;
    int lane = threadIdx.x & 31;
    if (gw >= N_NODES) return;
    int beg = g_off[gw], end = g_off[gw + 1];
    float a0 = 0.f, a1v = 0.f, a2v = 0.f, a3v = 0.f;
    float den = 0.f;
    int j = beg;
    for (; j + 1 < end; j += 2) {
        uint2 e0 = g_edge[j];
        uint2 e1 = g_edge[j + 1];
        uint2 hp0 = ((const uint2*)(g_h16 + (size_t)e0.x * 128))[lane];
        uint2 hp1 = ((const uint2*)(g_h16 + (size_t)e1.x * 128))[lane];
        float w0 = __uint_as_float(e0.y);
        float w1 = __uint_as_float(e1.y);
        float2 f0 = __half22float2(*(const __half2*)&hp0.x);
        float2 f1 = __half22float2(*(const __half2*)&hp0.y);
        float2 g0 = __half22float2(*(const __half2*)&hp1.x);
        float2 g1 = __half22float2(*(const __half2*)&hp1.y);
        a0 += w0 * f0.x + w1 * g0.x;
        a1v += w0 * f0.y + w1 * g0.y;
        a2v += w0 * f1.x + w1 * g1.x;
        a3v += w0 * f1.y + w1 * g1.y;
        den += w0 + w1;
    }
    if (j < end) {
        uint2 e = g_edge[j];
        float we = __uint_as_float(e.y);
        uint2 hp = ((const uint2*)(g_h16 + (size_t)e.x * 128))[lane];
        float2 f0 = __half22float2(*(const __half2*)&hp.x);
        float2 f1 = __half22float2(*(const __half2*)&hp.y);
        a0 += we * f0.x; a1v += we * f0.y;
        a2v += we * f1.x; a3v += we * f1.y;
        den += we;
    }
    float4 a = ((const float4*)g_a1)[lane];
    float4 b = ((const float4*)g_b1)[lane];
    float4 v;
    if (den != 0.f) {
        float inv = 1.f / den;
        v.x = a.x * (a0 * inv) + b.x;
        v.y = a.y * (a1v * inv) + b.y;
        v.z = a.z * (a2v * inv) + b.z;
        v.w = a.w * (a3v * inv) + b.w;
    } else {
        uint2 hp = ((const uint2*)(g_h16 + (size_t)gw * 128))[lane];
        float2 f0 = __half22float2(*(const __half2*)&hp.x);
        float2 f1 = __half22float2(*(const __half2*)&hp.y);
        v.x = a.x * f0.x + b.x;
        v.y = a.y * f0.y + b.y;
        v.z = a.z * f1.x + b.z;
        v.w = a.w * f1.y + b.w;
    }
    ((float4*)g_agg)[(size_t)gw * 32 + lane] = v;
}

// ================= BN2 + L2 normalize =================
__global__ void final_kernel(float* __restrict__ out) {
    int gw = (blockIdx.x * blockDim.x + threadIdx.x) >> 5;
    int lane = threadIdx.x & 31;
    if (gw >= N_NODES) return;
    float4 a = ((const float4*)g_a2)[lane];
    float4 b = ((const float4*)g_b2)[lane];
    float4 v = ((const float4*)g_rst)[(size_t)gw * 32 + lane];
    v.x = v.x * a.x + b.x; v.y = v.y * a.y + b.y;
    v.z = v.z * a.z + b.z; v.w = v.w * a.w + b.w;
    float ss = v.x * v.x + v.y * v.y + v.z * v.z + v.w * v.w;
#pragma unroll
    for (int o = 16; o > 0; o >>= 1) ss += __shfl_xor_sync(0xFFFFFFFFu, ss, o);
    float norm = sqrtf(ss);
    float inv = (norm == 0.f) ? 1.f : 1.f / norm;
    v.x *= inv; v.y *= inv; v.z *= inv; v.w *= inv;
    ((float4*)out)[(size_t)gw * 32 + lane] = v;
}

extern "C" void kernel_launch(void* const* d_in, const int* in_sizes, int n_in,
                              void* d_out, int out_size) {
    const float* feat  = (const float*)d_in[0];
    const float* w     = (const float*)d_in[1];
    const float* Qw    = (const float*)d_in[2];
    const float* Qb    = (const float*)d_in[3];
    const float* Ww    = (const float*)d_in[4];
    const float* Wb    = (const float*)d_in[5];
    const float* gamma = (const float*)d_in[6];
    const float* beta  = (const float*)d_in[7];
    const int* src     = (const int*)d_in[8];
    const int* dst     = (const int*)d_in[9];
    const int E = in_sizes[1];
    float* out = (float*)d_out;

    static int smem_set = 0;
    if (!smem_set) {
        cudaFuncSetAttribute(hmma_gemm<0>, cudaFuncAttributeMaxDynamicSharedMemorySize, SM_TOTAL);
        cudaFuncSetAttribute(hmma_gemm<1>, cudaFuncAttributeMaxDynamicSharedMemorySize, SM_TOTAL);
        smem_set = 1;
    }

    const int tile_grid = (N_NODES + 127) / 128;        // 391
    const int warp_grid = (N_NODES * 32 + 255) / 256;   // 6250
    const int e_grid = (E + 255) / 256;

    zero_kernel<<<128, 256>>>();
    hist_kernel<<<e_grid, 256>>>(dst, E);
    prefix_kernel<<<1, 1024>>>();
    scatter_kernel<<<e_grid, 256>>>(w, src, dst, E);
    prep_B<<<192, 256>>>(Qw, Ww);
    hmma_gemm<0><<<tile_grid, 256, SM_TOTAL>>>(feat, Qb);
    stats16_kernel<<<128, 256>>>();
    bn_params<<<1, 128>>>(0, gamma, beta);
    gather_kernel<<<warp_grid, 256>>>();
    hmma_gemm<1><<<tile_grid, 256, SM_TOTAL>>>(feat, Wb);
    stats32_kernel<<<128, 256>>>();
    bn_params<<<1, 128>>>(1, gamma, beta);
    final_kernel<<<warp_grid, 256>>>(out);
}

// round 11
// speedup vs baseline: 1.4516x; 1.1400x over previous
#include <cuda_runtime.h>
#include <cuda_fp16.h>
#include <math.h>
#include <stdint.h>

#define N_NODES 50000
#define D 128
#define EPS 1e-5f
#define E_MAX 800000

// padded fp16 tile: 128 rows x 64 cols, row stride 72 elems (144B = 9*16B -> bank rotate)
#define TROW 144
#define TILE_BYTES (128 * TROW)   // 18432

// ================= scratch (allocation-free: __device__ globals) =================
__device__ __half g_h16[N_NODES * D];   // fp16 hidden (consumers: gather, stats16)
__device__ float g_agg[N_NODES * D];
__device__ float g_rst[N_NODES * D];
__device__ int   g_cnt[N_NODES];
__device__ int   g_off[N_NODES + 1];
__device__ uint2 g_edge[E_MAX];         // packed (src, w_bits), dst-sorted
__device__ float g_sum1[D], g_sq1[D], g_sum2[D], g_sq2[D];
// single-precision-pass fp16 weight images, padded tile layout
__device__ unsigned char g_B1img[2][TILE_BYTES];
__device__ unsigned char g_B2img[4][TILE_BYTES];

// ================= warp-mma helpers =================
__device__ __forceinline__ uint32_t smem_u32(const void* p) {
    uint32_t a;
    asm("{ .reg .u64 t; cvta.to.shared.u64 t, %1; cvt.u32.u64 %0, t; }" : "=r"(a) : "l"(p));
    return a;
}
__device__ __forceinline__ void ldsm_x4(uint32_t* r, uint32_t addr) {
    asm volatile("ldmatrix.sync.aligned.m8n8.x4.shared.b16 {%0,%1,%2,%3}, [%4];"
                 : "=r"(r[0]), "=r"(r[1]), "=r"(r[2]), "=r"(r[3]) : "r"(addr));
}
__device__ __forceinline__ void mma_f16(float* d, const uint32_t* a, const uint32_t* b) {
    asm volatile(
        "mma.sync.aligned.m16n8k16.row.col.f32.f16.f16.f32 "
        "{%0,%1,%2,%3}, {%4,%5,%6,%7}, {%8,%9}, {%0,%1,%2,%3};"
        : "+f"(d[0]), "+f"(d[1]), "+f"(d[2]), "+f"(d[3])
        : "r"(a[0]), "r"(a[1]), "r"(a[2]), "r"(a[3]), "r"(b[0]), "r"(b[1]));
}

// ================= zero per-replay accumulators =================
__global__ void zero_kernel() {
    int idx = blockIdx.x * blockDim.x + threadIdx.x;
    int tot = blockDim.x * gridDim.x;
    for (int i = idx; i < N_NODES; i += tot) g_cnt[i] = 0;
    if (idx < D) { g_sum1[idx] = 0.f; g_sq1[idx] = 0.f; g_sum2[idx] = 0.f; g_sq2[idx] = 0.f; }
}

// ================= weight prep: fp32 -> fp16, padded tile layout =================
__global__ void prep_B(const float* __restrict__ Qw, const float* __restrict__ Ww) {
    int idx = blockIdx.x * blockDim.x + threadIdx.x;
    if (idx < 16384) {
        int r = idx >> 7, k = idx & 127;
        int chunk = k >> 6, kk = k & 63;
        *(__half*)(&g_B1img[chunk][(uint32_t)(r * TROW + kk * 2)]) =
            __float2half_rn(Qw[r * 128 + k]);
    } else if (idx < 16384 + 32768) {
        int e = idx - 16384;
        int r = e >> 8, k = e & 255;
        int chunk = k >> 6, kk = k & 63;
        *(__half*)(&g_B2img[chunk][(uint32_t)(r * TROW + kk * 2)]) =
            __float2half_rn(Ww[r * 256 + k]);
    }
}

// ================= HMMA GEMM (single-pass fp16): C = relu(A_concat @ B^T + bias) =================
#define SM_BIAS 0
#define SM_A    1024
#define SM_B    (1024 + TILE_BYTES)
#define SM_TOTAL (1024 + 2 * TILE_BYTES)   // 37888

template <int PHASE>
__global__ __launch_bounds__(256) void hmma_gemm(const float* __restrict__ A,
                                                 const float* __restrict__ bias) {
    extern __shared__ char smem[];
    const uint32_t sbase = smem_u32(smem);
    const int tid = threadIdx.x;
    const int wid = tid >> 5;
    const int lane = tid & 31;
    const int r0 = blockIdx.x * 128;
    const int NC = (PHASE == 0) ? 2 : 4;

    if (tid < 128) *(float*)(smem + SM_BIAS + tid * 4) = bias[tid];

    const int frow = tid >> 1;
    const int fhalf = tid & 1;
    const bool fvalid = (r0 + frow < N_NODES);

    const int warp_m = wid & 3;
    const int warp_n = wid >> 2;
    const uint32_t a_off = (uint32_t)((warp_m * 32 + (lane & 15)) * TROW + (lane >> 4) * 16);
    const uint32_t b_off = (uint32_t)((warp_n * 64 + (lane & 7) + ((lane >> 4) << 3)) * TROW
                                      + ((lane >> 3) & 1) * 16);

    float acc[2][8][4];
#pragma unroll
    for (int mt = 0; mt < 2; mt++)
#pragma unroll
        for (int nt = 0; nt < 8; nt++)
#pragma unroll
            for (int q = 0; q < 4; q++) acc[mt][nt][q] = 0.f;

    for (int c = 0; c < NC; c++) {
        const float* Asrc;
        int kbase;
        if (PHASE == 0) { Asrc = A; kbase = c * 64; }
        else if (c < 2) { Asrc = A; kbase = c * 64; }
        else            { Asrc = g_agg; kbase = (c - 2) * 64; }

        // A tile fill: fp32 -> fp16, 8 float4 per thread
        const float* rp = Asrc + (size_t)(fvalid ? (r0 + frow) : 0) * 128 + kbase + fhalf * 32;
#pragma unroll
        for (int i = 0; i < 8; i++) {
            float4 v = fvalid ? *(const float4*)(rp + i * 4) : make_float4(0.f, 0.f, 0.f, 0.f);
            uint32_t off = (uint32_t)(frow * TROW + (fhalf * 32 + i * 4) * 2);
            *(__half2*)(smem + SM_A + off) = __floats2half2_rn(v.x, v.y);
            *(__half2*)(smem + SM_A + off + 4) = __floats2half2_rn(v.z, v.w);
        }
        // B tile copy (pre-formatted fp16 image)
        {
            const float4* bsrc = (PHASE == 0) ? (const float4*)g_B1img[c] : (const float4*)g_B2img[c];
            float4* bdst = (float4*)(smem + SM_B);
            const int nf4 = TILE_BYTES / 16;   // 1152
            for (int j = tid; j < nf4; j += 256) bdst[j] = bsrc[j];
        }
        __syncthreads();

#pragma unroll
        for (int ks = 0; ks < 4; ks++) {
            uint32_t a[2][4];
#pragma unroll
            for (int mt = 0; mt < 2; mt++)
                ldsm_x4(a[mt], sbase + SM_A + a_off + mt * (16 * TROW) + ks * 32);
            uint32_t b[4][4];
#pragma unroll
            for (int ng = 0; ng < 4; ng++)
                ldsm_x4(b[ng], sbase + SM_B + b_off + ng * (16 * TROW) + ks * 32);
#pragma unroll
            for (int mt = 0; mt < 2; mt++)
#pragma unroll
                for (int ng = 0; ng < 4; ng++) {
                    mma_f16(acc[mt][ng * 2 + 0], a[mt], &b[ng][0]);
                    mma_f16(acc[mt][ng * 2 + 1], a[mt], &b[ng][2]);
                }
        }
        __syncthreads();
    }

    // ---- epilogue: bias + relu + store (fp16 phase0 / fp32 phase1) ----
    const int er = r0 + warp_m * 32 + (lane >> 2);
    const int ec = warp_n * 64 + (lane & 3) * 2;
#pragma unroll
    for (int mt = 0; mt < 2; mt++) {
#pragma unroll
        for (int nt = 0; nt < 8; nt++) {
            int col = ec + nt * 8;
            float bx = *(float*)(smem + SM_BIAS + col * 4);
            float by = *(float*)(smem + SM_BIAS + (col + 1) * 4);
#pragma unroll
            for (int half = 0; half < 2; half++) {
                int row = er + mt * 16 + half * 8;
                if (row < N_NODES) {
                    float x = fmaxf(acc[mt][nt][half * 2 + 0] + bx, 0.f);
                    float y = fmaxf(acc[mt][nt][half * 2 + 1] + by, 0.f);
                    if (PHASE == 0) {
                        *(__half2*)(g_h16 + (size_t)row * 128 + col) = __floats2half2_rn(x, y);
                    } else {
                        float2 v; v.x = x; v.y = y;
                        *(float2*)(g_rst + (size_t)row * 128 + col) = v;
                    }
                }
            }
        }
    }
}

// ================= column stats (phase 0: fp16 input) =================
__global__ void stats16_kernel() {
    __shared__ float s_s[128], s_q[128];
    int tid = threadIdx.x;
    if (tid < 128) { s_s[tid] = 0.f; s_q[tid] = 0.f; }
    __syncthreads();
    int lane = tid & 31;
    int wg = (blockIdx.x * blockDim.x + tid) >> 5;
    int wt = (gridDim.x * blockDim.x) >> 5;
    float4 s = make_float4(0.f, 0.f, 0.f, 0.f);
    float4 q = make_float4(0.f, 0.f, 0.f, 0.f);
    for (int r = wg; r < N_NODES; r += wt) {
        uint2 hp = ((const uint2*)(g_h16 + (size_t)r * 128))[lane];
        float2 f0 = __half22float2(*(const __half2*)&hp.x);
        float2 f1 = __half22float2(*(const __half2*)&hp.y);
        s.x += f0.x; s.y += f0.y; s.z += f1.x; s.w += f1.y;
        q.x += f0.x * f0.x; q.y += f0.y * f0.y;
        q.z += f1.x * f1.x; q.w += f1.y * f1.y;
    }
    atomicAdd(&s_s[lane * 4 + 0], s.x); atomicAdd(&s_s[lane * 4 + 1], s.y);
    atomicAdd(&s_s[lane * 4 + 2], s.z); atomicAdd(&s_s[lane * 4 + 3], s.w);
    atomicAdd(&s_q[lane * 4 + 0], q.x); atomicAdd(&s_q[lane * 4 + 1], q.y);
    atomicAdd(&s_q[lane * 4 + 2], q.z); atomicAdd(&s_q[lane * 4 + 3], q.w);
    __syncthreads();
    if (tid < 128) {
        atomicAdd(&g_sum1[tid], s_s[tid]);
        atomicAdd(&g_sq1[tid], s_q[tid]);
    }
}

// ================= column stats (phase 1: fp32 g_rst) =================
__global__ void stats32_kernel() {
    __shared__ float s_s[128], s_q[128];
    int tid = threadIdx.x;
    if (tid < 128) { s_s[tid] = 0.f; s_q[tid] = 0.f; }
    __syncthreads();
    int lane = tid & 31;
    int wg = (blockIdx.x * blockDim.x + tid) >> 5;
    int wt = (gridDim.x * blockDim.x) >> 5;
    float4 s = make_float4(0.f, 0.f, 0.f, 0.f);
    float4 q = make_float4(0.f, 0.f, 0.f, 0.f);
    for (int r = wg; r < N_NODES; r += wt) {
        float4 v = ((const float4*)g_rst)[(size_t)r * 32 + lane];
        s.x += v.x; s.y += v.y; s.z += v.z; s.w += v.w;
        q.x += v.x * v.x; q.y += v.y * v.y; q.z += v.z * v.z; q.w += v.w * v.w;
    }
    atomicAdd(&s_s[lane * 4 + 0], s.x); atomicAdd(&s_s[lane * 4 + 1], s.y);
    atomicAdd(&s_s[lane * 4 + 2], s.z); atomicAdd(&s_s[lane * 4 + 3], s.w);
    atomicAdd(&s_q[lane * 4 + 0], q.x); atomicAdd(&s_q[lane * 4 + 1], q.y);
    atomicAdd(&s_q[lane * 4 + 2], q.z); atomicAdd(&s_q[lane * 4 + 3], q.w);
    __syncthreads();
    if (tid < 128) {
        atomicAdd(&g_sum2[tid], s_s[tid]);
        atomicAdd(&g_sq2[tid], s_q[tid]);
    }
}

// ================= CSR build =================
__global__ void hist_kernel(const int* __restrict__ dst, int E) {
    int i = blockIdx.x * blockDim.x + threadIdx.x;
    if (i < E) atomicAdd(&g_cnt[dst[i]], 1);
}

__global__ __launch_bounds__(1024) void prefix_kernel() {
    __shared__ int wsum[32];
    __shared__ int carry;
    int tid = threadIdx.x, lane = tid & 31, wid = tid >> 5;
    if (tid == 0) { carry = 0; g_off[0] = 0; }
    __syncthreads();
    for (int base = 0; base < N_NODES; base += 4096) {
        int i0 = base + tid * 4;
        int v[4];
#pragma unroll
        for (int j = 0; j < 4; j++) v[j] = (i0 + j < N_NODES) ? g_cnt[i0 + j] : 0;
        int local = v[0] + v[1] + v[2] + v[3];
        int x = local;
#pragma unroll
        for (int o = 1; o < 32; o <<= 1) {
            int y = __shfl_up_sync(0xFFFFFFFFu, x, o);
            if (lane >= o) x += y;
        }
        if (lane == 31) wsum[wid] = x;
        __syncthreads();
        if (wid == 0) {
            int s = wsum[lane];
#pragma unroll
            for (int o = 1; o < 32; o <<= 1) {
                int y = __shfl_up_sync(0xFFFFFFFFu, s, o);
                if (lane >= o) s += y;
            }
            wsum[lane] = s;
        }
        __syncthreads();
        int wbase = (wid == 0) ? 0 : wsum[wid - 1];
        int run = carry + wbase + x - local;
#pragma unroll
        for (int j = 0; j < 4; j++) {
            int i = i0 + j;
            if (i < N_NODES) {
                g_cnt[i] = run;
                g_off[i + 1] = run + v[j];
            }
            run += v[j];
        }
        __syncthreads();
        if (tid == 0) carry += wsum[31];
        __syncthreads();
    }
}

__global__ void scatter_kernel(const float* __restrict__ w, const int* __restrict__ src,
                               const int* __restrict__ dst, int E) {
    int i = blockIdx.x * blockDim.x + threadIdx.x;
    if (i >= E) return;
    int d = dst[i];
    int pos = atomicAdd(&g_cnt[d], 1);
    g_edge[pos] = make_uint2((uint32_t)src[i], __float_as_uint(w[i]));
}

// ================= gather + per-block BN1 params + fold: warp per dst node =================
__global__ void gather_kernel(const float* __restrict__ gamma, const float* __restrict__ beta) {
    __shared__ __align__(16) float s_a[128];
    __shared__ __align__(16) float s_b[128];
    int tid = threadIdx.x;
    if (tid < 128) {
        float mean = g_sum1[tid] * (1.f / N_NODES);
        float var = g_sq1[tid] * (1.f / N_NODES) - mean * mean;
        float av = gamma[tid] * rsqrtf(var + EPS);
        s_a[tid] = av;
        s_b[tid] = beta[tid] - mean * av;
    }
    __syncthreads();

    int gw = (blockIdx.x * blockDim.x + tid) >> 5;
    int lane = tid & 31;
    if (gw >= N_NODES) return;
    int beg = g_off[gw], end = g_off[gw + 1];
    float a0 = 0.f, a1v = 0.f, a2v = 0.f, a3v = 0.f;
    float den = 0.f;
    int j = beg;
    for (; j + 1 < end; j += 2) {
        uint2 e0 = g_edge[j];
        uint2 e1 = g_edge[j + 1];
        uint2 hp0 = ((const uint2*)(g_h16 + (size_t)e0.x * 128))[lane];
        uint2 hp1 = ((const uint2*)(g_h16 + (size_t)e1.x * 128))[lane];
        float w0 = __uint_as_float(e0.y);
        float w1 = __uint_as_float(e1.y);
        float2 f0 = __half22float2(*(const __half2*)&hp0.x);
        float2 f1 = __half22float2(*(const __half2*)&hp0.y);
        float2 g0 = __half22float2(*(const __half2*)&hp1.x);
        float2 g1 = __half22float2(*(const __half2*)&hp1.y);
        a0 += w0 * f0.x + w1 * g0.x;
        a1v += w0 * f0.y + w1 * g0.y;
        a2v += w0 * f1.x + w1 * g1.x;
        a3v += w0 * f1.y + w1 * g1.y;
        den += w0 + w1;
    }
    if (j < end) {
        uint2 e = g_edge[j];
        float we = __uint_as_float(e.y);
        uint2 hp = ((const uint2*)(g_h16 + (size_t)e.x * 128))[lane];
        float2 f0 = __half22float2(*(const __half2*)&hp.x);
        float2 f1 = __half22float2(*(const __half2*)&hp.y);
        a0 += we * f0.x; a1v += we * f0.y;
        a2v += we * f1.x; a3v += we * f1.y;
        den += we;
    }
    float4 a = *(const float4*)&s_a[lane * 4];
    float4 b = *(const float4*)&s_b[lane * 4];
    float4 v;
    if (den != 0.f) {
        float inv = 1.f / den;
        v.x = a.x * (a0 * inv) + b.x;
        v.y = a.y * (a1v * inv) + b.y;
        v.z = a.z * (a2v * inv) + b.z;
        v.w = a.w * (a3v * inv) + b.w;
    } else {
        uint2 hp = ((const uint2*)(g_h16 + (size_t)gw * 128))[lane];
        float2 f0 = __half22float2(*(const __half2*)&hp.x);
        float2 f1 = __half22float2(*(const __half2*)&hp.y);
        v.x = a.x * f0.x + b.x;
        v.y = a.y * f0.y + b.y;
        v.z = a.z * f1.x + b.z;
        v.w = a.w * f1.y + b.w;
    }
    ((float4*)g_agg)[(size_t)gw * 32 + lane] = v;
}

// ================= final: per-block BN2 params + BN2 + L2 normalize =================
__global__ void final_kernel(float* __restrict__ out, const float* __restrict__ gamma,
                             const float* __restrict__ beta) {
    __shared__ __align__(16) float s_a[128];
    __shared__ __align__(16) float s_b[128];
    int tid = threadIdx.x;
    if (tid < 128) {
        float mean = g_sum2[tid] * (1.f / N_NODES);
        float var = g_sq2[tid] * (1.f / N_NODES) - mean * mean;
        float av = gamma[tid] * rsqrtf(var + EPS);
        s_a[tid] = av;
        s_b[tid] = beta[tid] - mean * av;
    }
    __syncthreads();

    int gw = (blockIdx.x * blockDim.x + tid) >> 5;
    int lane = tid & 31;
    if (gw >= N_NODES) return;
    float4 a = *(const float4*)&s_a[lane * 4];
    float4 b = *(const float4*)&s_b[lane * 4];
    float4 v = ((const float4*)g_rst)[(size_t)gw * 32 + lane];
    v.x = v.x * a.x + b.x; v.y = v.y * a.y + b.y;
    v.z = v.z * a.z + b.z; v.w = v.w * a.w + b.w;
    float ss = v.x * v.x + v.y * v.y + v.z * v.z + v.w * v.w;
#pragma unroll
    for (int o = 16; o > 0; o >>= 1) ss += __shfl_xor_sync(0xFFFFFFFFu, ss, o);
    float norm = sqrtf(ss);
    float inv = (norm == 0.f) ? 1.f : 1.f / norm;
    v.x *= inv; v.y *= inv; v.z *= inv; v.w *= inv;
    ((float4*)out)[(size_t)gw * 32 + lane] = v;
}

extern "C" void kernel_launch(void* const* d_in, const int* in_sizes, int n_in,
                              void* d_out, int out_size) {
    const float* feat  = (const float*)d_in[0];
    const float* w     = (const float*)d_in[1];
    const float* Qw    = (const float*)d_in[2];
    const float* Qb    = (const float*)d_in[3];
    const float* Ww    = (const float*)d_in[4];
    const float* Wb    = (const float*)d_in[5];
    const float* gamma = (const float*)d_in[6];
    const float* beta  = (const float*)d_in[7];
    const int* src     = (const int*)d_in[8];
    const int* dst     = (const int*)d_in[9];
    const int E = in_sizes[1];
    float* out = (float*)d_out;

    static int smem_set = 0;
    if (!smem_set) {
        cudaFuncSetAttribute(hmma_gemm<0>, cudaFuncAttributeMaxDynamicSharedMemorySize, SM_TOTAL);
        cudaFuncSetAttribute(hmma_gemm<1>, cudaFuncAttributeMaxDynamicSharedMemorySize, SM_TOTAL);
        smem_set = 1;
    }

    const int tile_grid = (N_NODES + 127) / 128;        // 391
    const int warp_grid = (N_NODES * 32 + 255) / 256;   // 6250
    const int e_grid = (E + 255) / 256;

    zero_kernel<<<128, 256>>>();
    hist_kernel<<<e_grid, 256>>>(dst, E);
    prefix_kernel<<<1, 1024>>>();
    scatter_kernel<<<e_grid, 256>>>(w, src, dst, E);
    prep_B<<<192, 256>>>(Qw, Ww);
    hmma_gemm<0><<<tile_grid, 256, SM_TOTAL>>>(feat, Qb);
    stats16_kernel<<<128, 256>>>();
    gather_kernel<<<warp_grid, 256>>>(gamma, beta);
    hmma_gemm<1><<<tile_grid, 256, SM_TOTAL>>>(feat, Wb);
    stats32_kernel<<<128, 256>>>();
    final_kernel<<<warp_grid, 256>>>(out, gamma, beta);
}

// round 13
// speedup vs baseline: 1.4650x; 1.0092x over previous
#include <cuda_runtime.h>
#include <cuda_fp16.h>
#include <math.h>
#include <stdint.h>

#define N_NODES 50000
#define D 128
#define EPS 1e-5f
#define E_MAX 800000

// padded fp16 tile: rows x 64 cols, row stride 72 elems (144B = 9*16B -> bank rotate)
#define TROW 144
#define TILE_BYTES (128 * TROW)   // 18432
#define PADROWS 50048             // 391 tiles * 128

// ================= scratch (allocation-free: __device__ globals) =================
__device__ __half g_h16[N_NODES * D];   // fp16 hidden (consumers: gather, stats16)
__device__ float g_rst[N_NODES * D];
__device__ int   g_cnt[N_NODES];
__device__ int   g_off[N_NODES + 1];
__device__ uint2 g_edge[E_MAX];         // packed (src, w_bits), dst-sorted
__device__ float g_sum1[D], g_sq1[D], g_sum2[D], g_sq2[D];
// pre-formatted fp16 operand images (padded tile layout, pure-copy GEMM fills)
__device__ __align__(16) unsigned char g_B1img[2][TILE_BYTES];
__device__ __align__(16) unsigned char g_B2img[4][TILE_BYTES];
__device__ __align__(16) unsigned char g_featimg[2][PADROWS * TROW];
__device__ __align__(16) unsigned char g_aggimg[2][PADROWS * TROW];

// ================= warp-mma helpers =================
__device__ __forceinline__ uint32_t smem_u32(const void* p) {
    uint32_t a;
    asm("{ .reg .u64 t; cvta.to.shared.u64 t, %1; cvt.u32.u64 %0, t; }" : "=r"(a) : "l"(p));
    return a;
}
__device__ __forceinline__ void ldsm_x4(uint32_t* r, uint32_t addr) {
    asm volatile("ldmatrix.sync.aligned.m8n8.x4.shared.b16 {%0,%1,%2,%3}, [%4];"
                 : "=r"(r[0]), "=r"(r[1]), "=r"(r[2]), "=r"(r[3]) : "r"(addr));
}
__device__ __forceinline__ void mma_f16(float* d, const uint32_t* a, const uint32_t* b) {
    asm volatile(
        "mma.sync.aligned.m16n8k16.row.col.f32.f16.f16.f32 "
        "{%0,%1,%2,%3}, {%4,%5,%6,%7}, {%8,%9}, {%0,%1,%2,%3};"
        : "+f"(d[0]), "+f"(d[1]), "+f"(d[2]), "+f"(d[3])
        : "r"(a[0]), "r"(a[1]), "r"(a[2]), "r"(a[3]), "r"(b[0]), "r"(b[1]));
}

// ================= zero per-replay accumulators =================
__global__ void zero_kernel() {
    int idx = blockIdx.x * blockDim.x + threadIdx.x;
    int tot = blockDim.x * gridDim.x;
    for (int i = idx; i < N_NODES; i += tot) g_cnt[i] = 0;
    if (idx < D) { g_sum1[idx] = 0.f; g_sq1[idx] = 0.f; g_sum2[idx] = 0.f; g_sq2[idx] = 0.f; }
}

// ================= feat fp32 -> fp16 image (padded tile layout) =================
__global__ void conv_feat(const float* __restrict__ feat) {
    int idx = blockIdx.x * blockDim.x + threadIdx.x;
    if (idx >= N_NODES * 32) return;
    int node = idx >> 5, lane = idx & 31;
    float4 v = ((const float4*)feat)[(size_t)node * 32 + lane];
    __half2 p0 = __floats2half2_rn(v.x, v.y);
    __half2 p1 = __floats2half2_rn(v.z, v.w);
    int chunk = lane >> 4;
    int cin = (lane * 4) & 63;
    *(uint2*)(&g_featimg[chunk][(size_t)node * TROW + cin * 2]) =
        make_uint2(*(uint32_t*)&p0, *(uint32_t*)&p1);
}

// ================= weight prep: fp32 -> fp16, padded tile layout =================
__global__ void prep_B(const float* __restrict__ Qw, const float* __restrict__ Ww) {
    int idx = blockIdx.x * blockDim.x + threadIdx.x;
    if (idx < 16384) {
        int r = idx >> 7, k = idx & 127;
        int chunk = k >> 6, kk = k & 63;
        *(__half*)(&g_B1img[chunk][(uint32_t)(r * TROW + kk * 2)]) =
            __float2half_rn(Qw[r * 128 + k]);
    } else if (idx < 16384 + 32768) {
        int e = idx - 16384;
        int r = e >> 8, k = e & 255;
        int chunk = k >> 6, kk = k & 63;
        *(__half*)(&g_B2img[chunk][(uint32_t)(r * TROW + kk * 2)]) =
            __float2half_rn(Ww[r * 256 + k]);
    }
}

// ================= HMMA GEMM (fp16, pure-copy fills): C = relu(A @ B^T + bias) =================
#define SM_BIAS 0
#define SM_A    1024
#define SM_B    (1024 + TILE_BYTES)
#define SM_TOTAL (1024 + 2 * TILE_BYTES)   // 37888

template <int PHASE>
__global__ __launch_bounds__(256) void hmma_gemm(const float* __restrict__ bias) {
    extern __shared__ char smem[];
    const uint32_t sbase = smem_u32(smem);
    const int tid = threadIdx.x;
    const int wid = tid >> 5;
    const int lane = tid & 31;
    const int r0 = blockIdx.x * 128;
    const int NC = (PHASE == 0) ? 2 : 4;

    if (tid < 128) *(float*)(smem + SM_BIAS + tid * 4) = bias[tid];

    const int warp_m = wid & 3;
    const int warp_n = wid >> 2;
    const uint32_t a_off = (uint32_t)((warp_m * 32 + (lane & 15)) * TROW + (lane >> 4) * 16);
    const uint32_t b_off = (uint32_t)((warp_n * 64 + (lane & 7) + ((lane >> 4) << 3)) * TROW
                                      + ((lane >> 3) & 1) * 16);

    float acc[2][8][4];
#pragma unroll
    for (int mt = 0; mt < 2; mt++)
#pragma unroll
        for (int nt = 0; nt < 8; nt++)
#pragma unroll
            for (int q = 0; q < 4; q++) acc[mt][nt][q] = 0.f;

    for (int c = 0; c < NC; c++) {
        // A + B tile fills: pure float4 copies of pre-formatted fp16 images
        const unsigned char* imgA;
        if (PHASE == 0) imgA = g_featimg[c];
        else            imgA = (c < 2) ? g_featimg[c] : g_aggimg[c - 2];
        {
            const float4* asrc = (const float4*)(imgA + (size_t)r0 * TROW);
            const float4* bsrc = (PHASE == 0) ? (const float4*)g_B1img[c]
                                              : (const float4*)g_B2img[c];
            float4* adst = (float4*)(smem + SM_A);
            float4* bdst = (float4*)(smem + SM_B);
            const int nf4 = TILE_BYTES / 16;   // 1152
            for (int j = tid; j < nf4; j += 256) {
                adst[j] = asrc[j];
                bdst[j] = bsrc[j];
            }
        }
        __syncthreads();

#pragma unroll
        for (int ks = 0; ks < 4; ks++) {
            uint32_t a[2][4];
#pragma unroll
            for (int mt = 0; mt < 2; mt++)
                ldsm_x4(a[mt], sbase + SM_A + a_off + mt * (16 * TROW) + ks * 32);
            uint32_t b[4][4];
#pragma unroll
            for (int ng = 0; ng < 4; ng++)
                ldsm_x4(b[ng], sbase + SM_B + b_off + ng * (16 * TROW) + ks * 32);
#pragma unroll
            for (int mt = 0; mt < 2; mt++)
#pragma unroll
                for (int ng = 0; ng < 4; ng++) {
                    mma_f16(acc[mt][ng * 2 + 0], a[mt], &b[ng][0]);
                    mma_f16(acc[mt][ng * 2 + 1], a[mt], &b[ng][2]);
                }
        }
        __syncthreads();
    }

    // ---- epilogue: bias + relu + store (fp16 h for phase0 / fp32 rst for phase1) ----
    const int er = r0 + warp_m * 32 + (lane >> 2);
    const int ec = warp_n * 64 + (lane & 3) * 2;
#pragma unroll
    for (int mt = 0; mt < 2; mt++) {
#pragma unroll
        for (int nt = 0; nt < 8; nt++) {
            int col = ec + nt * 8;
            float bx = *(float*)(smem + SM_BIAS + col * 4);
            float by = *(float*)(smem + SM_BIAS + (col + 1) * 4);
#pragma unroll
            for (int half = 0; half < 2; half++) {
                int row = er + mt * 16 + half * 8;
                if (row < N_NODES) {
                    float x = fmaxf(acc[mt][nt][half * 2 + 0] + bx, 0.f);
                    float y = fmaxf(acc[mt][nt][half * 2 + 1] + by, 0.f);
                    if (PHASE == 0) {
                        *(__half2*)(g_h16 + (size_t)row * 128 + col) = __floats2half2_rn(x, y);
                    } else {
                        float2 v; v.x = x; v.y = y;
                        *(float2*)(g_rst + (size_t)row * 128 + col) = v;
                    }
                }
            }
        }
    }
}

// ================= column stats (phase 0: fp16 input) =================
__global__ void stats16_kernel() {
    __shared__ float s_s[128], s_q[128];
    int tid = threadIdx.x;
    if (tid < 128) { s_s[tid] = 0.f; s_q[tid] = 0.f; }
    __syncthreads();
    int lane = tid & 31;
    int wg = (blockIdx.x * blockDim.x + tid) >> 5;
    int wt = (gridDim.x * blockDim.x) >> 5;
    float4 s = make_float4(0.f, 0.f, 0.f, 0.f);
    float4 q = make_float4(0.f, 0.f, 0.f, 0.f);
    for (int r = wg; r < N_NODES; r += wt) {
        uint2 hp = ((const uint2*)(g_h16 + (size_t)r * 128))[lane];
        float2 f0 = __half22float2(*(const __half2*)&hp.x);
        float2 f1 = __half22float2(*(const __half2*)&hp.y);
        s.x += f0.x; s.y += f0.y; s.z += f1.x; s.w += f1.y;
        q.x += f0.x * f0.x; q.y += f0.y * f0.y;
        q.z += f1.x * f1.x; q.w += f1.y * f1.y;
    }
    atomicAdd(&s_s[lane * 4 + 0], s.x); atomicAdd(&s_s[lane * 4 + 1], s.y);
    atomicAdd(&s_s[lane * 4 + 2], s.z); atomicAdd(&s_s[lane * 4 + 3], s.w);
    atomicAdd(&s_q[lane * 4 + 0], q.x); atomicAdd(&s_q[lane * 4 + 1], q.y);
    atomicAdd(&s_q[lane * 4 + 2], q.z); atomicAdd(&s_q[lane * 4 + 3], q.w);
    __syncthreads();
    if (tid < 128) {
        atomicAdd(&g_sum1[tid], s_s[tid]);
        atomicAdd(&g_sq1[tid], s_q[tid]);
    }
}

// ================= column stats (phase 1: fp32 g_rst) =================
__global__ void stats32_kernel() {
    __shared__ float s_s[128], s_q[128];
    int tid = threadIdx.x;
    if (tid < 128) { s_s[tid] = 0.f; s_q[tid] = 0.f; }
    __syncthreads();
    int lane = tid & 31;
    int wg = (blockIdx.x * blockDim.x + tid) >> 5;
    int wt = (gridDim.x * blockDim.x) >> 5;
    float4 s = make_float4(0.f, 0.f, 0.f, 0.f);
    float4 q = make_float4(0.f, 0.f, 0.f, 0.f);
    for (int r = wg; r < N_NODES; r += wt) {
        float4 v = ((const float4*)g_rst)[(size_t)r * 32 + lane];
        s.x += v.x; s.y += v.y; s.z += v.z; s.w += v.w;
        q.x += v.x * v.x; q.y += v.y * v.y; q.z += v.z * v.z; q.w += v.w * v.w;
    }
    atomicAdd(&s_s[lane * 4 + 0], s.x); atomicAdd(&s_s[lane * 4 + 1], s.y);
    atomicAdd(&s_s[lane * 4 + 2], s.z); atomicAdd(&s_s[lane * 4 + 3], s.w);
    atomicAdd(&s_q[lane * 4 + 0], q.x); atomicAdd(&s_q[lane * 4 + 1], q.y);
    atomicAdd(&s_q[lane * 4 + 2], q.z); atomicAdd(&s_q[lane * 4 + 3], q.w);
    __syncthreads();
    if (tid < 128) {
        atomicAdd(&g_sum2[tid], s_s[tid]);
        atomicAdd(&g_sq2[tid], s_q[tid]);
    }
}

// ================= CSR build =================
__global__ void hist_kernel(const int* __restrict__ dst, int E) {
    int i = blockIdx.x * blockDim.x + threadIdx.x;
    if (i < E) atomicAdd(&g_cnt[dst[i]], 1);
}

__global__ __launch_bounds__(1024) void prefix_kernel() {
    __shared__ int wsum[32];
    __shared__ int carry;
    int tid = threadIdx.x, lane = tid & 31, wid = tid >> 5;
    if (tid == 0) { carry = 0; g_off[0] = 0; }
    __syncthreads();
    for (int base = 0; base < N_NODES; base += 4096) {
        int i0 = base + tid * 4;
        int v[4];
#pragma unroll
        for (int j = 0; j < 4; j++) v[j] = (i0 + j < N_NODES) ? g_cnt[i0 + j] : 0;
        int local = v[0] + v[1] + v[2] + v[3];
        int x = local;
#pragma unroll
        for (int o = 1; o < 32; o <<= 1) {
            int y = __shfl_up_sync(0xFFFFFFFFu, x, o);
            if (lane >= o) x += y;
        }
        if (lane == 31) wsum[wid] = x;
        __syncthreads();
        if (wid == 0) {
            int s = wsum[lane];
#pragma unroll
            for (int o = 1; o < 32; o <<= 1) {
                int y = __shfl_up_sync(0xFFFFFFFFu, s, o);
                if (lane >= o) s += y;
            }
            wsum[lane] = s;
        }
        __syncthreads();
        int wbase = (wid == 0) ? 0 : wsum[wid - 1];
        int run = carry + wbase + x - local;
#pragma unroll
        for (int j = 0; j < 4; j++) {
            int i = i0 + j;
            if (i < N_NODES) {
                g_cnt[i] = run;
                g_off[i + 1] = run + v[j];
            }
            run += v[j];
        }
        __syncthreads();
        if (tid == 0) carry += wsum[31];
        __syncthreads();
    }
}

__global__ void scatter_kernel(const float* __restrict__ w, const int* __restrict__ src,
                               const int* __restrict__ dst, int E) {
    int i = blockIdx.x * blockDim.x + threadIdx.x;
    if (i >= E) return;
    int d = dst[i];
    int pos = atomicAdd(&g_cnt[d], 1);
    g_edge[pos] = make_uint2((uint32_t)src[i], __float_as_uint(w[i]));
}

// ================= gather + per-block BN1 params + fold -> fp16 agg image =================
__global__ void gather_kernel(const float* __restrict__ gamma, const float* __restrict__ beta) {
    __shared__ __align__(16) float s_a[128];
    __shared__ __align__(16) float s_b[128];
    int tid = threadIdx.x;
    if (tid < 128) {
        float mean = g_sum1[tid] * (1.f / N_NODES);
        float var = g_sq1[tid] * (1.f / N_NODES) - mean * mean;
        float av = gamma[tid] * rsqrtf(var + EPS);
        s_a[tid] = av;
        s_b[tid] = beta[tid] - mean * av;
    }
    __syncthreads();

    int gw = (blockIdx.x * blockDim.x + tid) >> 5;
    int lane = tid & 31;
    if (gw >= N_NODES) return;
    int beg = g_off[gw], end = g_off[gw + 1];
    float a0 = 0.f, a1v = 0.f, a2v = 0.f, a3v = 0.f;
    float den = 0.f;
    int j = beg;
    for (; j + 1 < end; j += 2) {
        uint2 e0 = g_edge[j];
        uint2 e1 = g_edge[j + 1];
        uint2 hp0 = ((const uint2*)(g_h16 + (size_t)e0.x * 128))[lane];
        uint2 hp1 = ((const uint2*)(g_h16 + (size_t)e1.x * 128))[lane];
        float w0 = __uint_as_float(e0.y);
        float w1 = __uint_as_float(e1.y);
        float2 f0 = __half22float2(*(const __half2*)&hp0.x);
        float2 f1 = __half22float2(*(const __half2*)&hp0.y);
        float2 g0 = __half22float2(*(const __half2*)&hp1.x);
        float2 g1 = __half22float2(*(const __half2*)&hp1.y);
        a0 += w0 * f0.x + w1 * g0.x;
        a1v += w0 * f0.y + w1 * g0.y;
        a2v += w0 * f1.x + w1 * g1.x;
        a3v += w0 * f1.y + w1 * g1.y;
        den += w0 + w1;
    }
    if (j < end) {
        uint2 e = g_edge[j];
        float we = __uint_as_float(e.y);
        uint2 hp = ((const uint2*)(g_h16 + (size_t)e.x * 128))[lane];
        float2 f0 = __half22float2(*(const __half2*)&hp.x);
        float2 f1 = __half22float2(*(const __half2*)&hp.y);
        a0 += we * f0.x; a1v += we * f0.y;
        a2v += we * f1.x; a3v += we * f1.y;
        den += we;
    }
    float4 a = *(const float4*)&s_a[lane * 4];
    float4 b = *(const float4*)&s_b[lane * 4];
    float4 v;
    if (den != 0.f) {
        float inv = 1.f / den;
        v.x = a.x * (a0 * inv) + b.x;
        v.y = a.y * (a1v * inv) + b.y;
        v.z = a.z * (a2v * inv) + b.z;
        v.w = a.w * (a3v * inv) + b.w;
    } else {
        uint2 hp = ((const uint2*)(g_h16 + (size_t)gw * 128))[lane];
        float2 f0 = __half22float2(*(const __half2*)&hp.x);
        float2 f1 = __half22float2(*(const __half2*)&hp.y);
        v.x = a.x * f0.x + b.x;
        v.y = a.y * f0.y + b.y;
        v.z = a.z * f1.x + b.z;
        v.w = a.w * f1.y + b.w;
    }
    // store fp16 into padded agg image (GEMM2 rounds to fp16 anyway -> bit-identical)
    __half2 p0 = __floats2half2_rn(v.x, v.y);
    __half2 p1 = __floats2half2_rn(v.z, v.w);
    int chunk = lane >> 4;
    int cin = (lane * 4) & 63;
    *(uint2*)(&g_aggimg[chunk][(size_t)gw * TROW + cin * 2]) =
        make_uint2(*(uint32_t*)&p0, *(uint32_t*)&p1);
}

// ================= final: per-block BN2 params + BN2 + L2 normalize =================
__global__ void final_kernel(float* __restrict__ out, const float* __restrict__ gamma,
                             const float* __restrict__ beta) {
    __shared__ __align__(16) float s_a[128];
    __shared__ __align__(16) float s_b[128];
    int tid = threadIdx.x;
    if (tid < 128) {
        float mean = g_sum2[tid] * (1.f / N_NODES);
        float var = g_sq2[tid] * (1.f / N_NODES) - mean * mean;
        float av = gamma[tid] * rsqrtf(var + EPS);
        s_a[tid] = av;
        s_b[tid] = beta[tid] - mean * av;
    }
    __syncthreads();

    int gw = (blockIdx.x * blockDim.x + tid) >> 5;
    int lane = tid & 31;
    if (gw >= N_NODES) return;
    float4 a = *(const float4*)&s_a[lane * 4];
    float4 b = *(const float4*)&s_b[lane * 4];
    float4 v = ((const float4*)g_rst)[(size_t)gw * 32 + lane];
    v.x = v.x * a.x + b.x; v.y = v.y * a.y + b.y;
    v.z = v.z * a.z + b.z; v.w = v.w * a.w + b.w;
    float ss = v.x * v.x + v.y * v.y + v.z * v.z + v.w * v.w;
#pragma unroll
    for (int o = 16; o > 0; o >>= 1) ss += __shfl_xor_sync(0xFFFFFFFFu, ss, o);
    float norm = sqrtf(ss);
    float inv = (norm == 0.f) ? 1.f : 1.f / norm;
    v.x *= inv; v.y *= inv; v.z *= inv; v.w *= inv;
    ((float4*)out)[(size_t)gw * 32 + lane] = v;
}

extern "C" void kernel_launch(void* const* d_in, const int* in_sizes, int n_in,
                              void* d_out, int out_size) {
    const float* feat  = (const float*)d_in[0];
    const float* w     = (const float*)d_in[1];
    const float* Qw    = (const float*)d_in[2];
    const float* Qb    = (const float*)d_in[3];
    const float* Ww    = (const float*)d_in[4];
    const float* Wb    = (const float*)d_in[5];
    const float* gamma = (const float*)d_in[6];
    const float* beta  = (const float*)d_in[7];
    const int* src     = (const int*)d_in[8];
    const int* dst     = (const int*)d_in[9];
    const int E = in_sizes[1];
    float* out = (float*)d_out;

    static int smem_set = 0;
    if (!smem_set) {
        cudaFuncSetAttribute(hmma_gemm<0>, cudaFuncAttributeMaxDynamicSharedMemorySize, SM_TOTAL);
        cudaFuncSetAttribute(hmma_gemm<1>, cudaFuncAttributeMaxDynamicSharedMemorySize, SM_TOTAL);
        smem_set = 1;
    }

    const int tile_grid = (N_NODES + 127) / 128;        // 391
    const int warp_grid = (N_NODES * 32 + 255) / 256;   // 6250
    const int e_grid = (E + 255) / 256;

    zero_kernel<<<128, 256>>>();
    hist_kernel<<<e_grid, 256>>>(dst, E);
    prefix_kernel<<<1, 1024>>>();
    scatter_kernel<<<e_grid, 256>>>(w, src, dst, E);
    conv_feat<<<warp_grid, 256>>>(feat);
    prep_B<<<192, 256>>>(Qw, Ww);
    hmma_gemm<0><<<tile_grid, 256, SM_TOTAL>>>(Qb);
    stats16_kernel<<<128, 256>>>();
    gather_kernel<<<warp_grid, 256>>>(gamma, beta);
    hmma_gemm<1><<<tile_grid, 256, SM_TOTAL>>>(Wb);
    stats32_kernel<<<128, 256>>>();
    final_kernel<<<warp_grid, 256>>>(out, gamma, beta);
}